// round 2
// baseline (speedup 1.0000x reference)
#include <cuda_runtime.h>
#include <cstdint>

// Problem constants (fixed by the dataset: N=2048, DIM=16, E=65536)
#define NN 2048
#define DD 16
#define BITMAP_WORDS ((NN * NN) / 32)   // 131072 words = 512 KB

// scratch (no cudaMalloc allowed)
__device__ float    g_a[NN];                 // dot(e[i], W[0:16])
__device__ float    g_c[NN];                 // dot(e[i], W[16:32])
__device__ unsigned g_bitmap[BITMAP_WORDS];  // adjacency bitmap

// ---------------------------------------------------------------------------
// Kernel 1: per-node dot products with the two halves of W, AND zero the
// bitmap (fused: grid covers max of both tasks).
// ---------------------------------------------------------------------------
__global__ void precompute_and_zero(const float* __restrict__ e,
                                    const float* __restrict__ W, int n) {
    int t = blockIdx.x * blockDim.x + threadIdx.x;
    if (t < n) {
        float a = 0.f, c = 0.f;
#pragma unroll
        for (int k = 0; k < DD; k++) {
            float v = __ldg(&e[t * DD + k]);
            a += v * __ldg(&W[k]);
            c += v * __ldg(&W[DD + k]);
        }
        g_a[t] = a;
        g_c[t] = c;
    }
    // zero bitmap: 131072 words, grid-stride from all threads
    for (int w = t; w < BITMAP_WORDS; w += gridDim.x * blockDim.x)
        g_bitmap[w] = 0u;
}

// ---------------------------------------------------------------------------
// Kernel 2: scatter true-edge bits into the bitmap
// edge_list layout: [2, E] row-major -> src = el[t], dst = el[E + t]
// ---------------------------------------------------------------------------
__global__ void scatter_bits(const int* __restrict__ el, int E, int n) {
    int t = blockIdx.x * blockDim.x + threadIdx.x;
    if (t >= E) return;
    unsigned p = (unsigned)el[t] * (unsigned)n + (unsigned)el[E + t];
    atomicOr(&g_bitmap[p >> 5], 1u << (p & 31u));
}

// ---------------------------------------------------------------------------
// Kernel 3 (the big one): writes everything.
// 4 threads per pair p = i*N + j. Thread k in [0,4):
//   node = (k<2) ? i : j, chunk = k&1  -> 32B of that node's row
//   stores emb_out[p*32 + k*8 .. +8) as two STG.128 (streaming)
// Lane k==0 writes logit[p]; lane k==1 writes te[p] from the bitmap.
// Warp = 8 consecutive pairs -> 1KB fully contiguous emb stores;
// logit/te writes are 8 consecutive floats per warp (one 32B sector each).
// ---------------------------------------------------------------------------
__global__ void __launch_bounds__(256)
write_all(const float4* __restrict__ e4,   // [N*4] float4 (row = 4 float4)
          float4* __restrict__ emb_out,    // [N*N*8] float4
          float* __restrict__ logit_out,   // [N*N]
          float* __restrict__ te_out,      // [N*N]
          const float* __restrict__ bptr) {
    unsigned t = blockIdx.x * blockDim.x + threadIdx.x;
    unsigned pair = t >> 2;
    unsigned k = t & 3u;
    unsigned i = pair >> 11;          // pair / 2048
    unsigned j = pair & 2047u;        // pair % 2048

    unsigned node = (k < 2u) ? i : j;
    unsigned src = node * 4u + (k & 1u) * 2u;   // float4 index into e4
    float4 v0 = __ldg(&e4[src]);
    float4 v1 = __ldg(&e4[src + 1]);

    float4* dst = emb_out + (size_t)pair * 8 + k * 2;
    __stcs(dst,     v0);
    __stcs(dst + 1, v1);

    if (k == 0u) {
        float lg = (i != j) ? (g_a[i] + g_c[j] + __ldg(bptr)) : -10.0f;
        __stcs(&logit_out[pair], lg);
    } else if (k == 1u) {
        unsigned bit = (g_bitmap[pair >> 5] >> (pair & 31u)) & 1u;
        __stcs(&te_out[pair], (float)bit);
    }
}

// ---------------------------------------------------------------------------
extern "C" void kernel_launch(void* const* d_in, const int* in_sizes, int n_in,
                              void* d_out, int out_size) {
    const float* emb   = (const float*)d_in[0];   // [N, 16]
    const int*   edges = (const int*)d_in[1];     // [2, E]
    const float* W     = (const float*)d_in[2];   // [1, 32]
    const float* b     = (const float*)d_in[3];   // [1]

    const int two_d = in_sizes[2];        // 32
    const int d     = two_d / 2;          // 16
    const int n     = in_sizes[0] / d;    // 2048
    const int E     = in_sizes[1] / 2;    // 65536

    float* out       = (float*)d_out;
    float* emb_out   = out;                                   // n*n*2d floats
    float* logit_out = out + (size_t)n * n * two_d;           // n*n floats
    float* te_out    = logit_out + (size_t)n * n;             // n*n floats

    // 1) per-node dots + bitmap zero (512 blocks x 256 covers both)
    precompute_and_zero<<<512, 256>>>(emb, W, n);

    // 2) scatter true-edge bits
    scatter_bits<<<(E + 255) / 256, 256>>>(edges, E, n);

    // 3) fused main write: 4 threads per pair
    unsigned threads_total = (unsigned)n * (unsigned)n * 4u;  // 16,777,216
    write_all<<<threads_total / 256, 256>>>((const float4*)emb,
                                            (float4*)emb_out,
                                            logit_out, te_out, b);
}